// round 6
// baseline (speedup 1.0000x reference)
#include <cuda_runtime.h>
#include <cuda_fp16.h>
#include <cstdint>

#define B_    4
#define S_    2048
#define DIN   2048
#define DOUT  2048
#define M_TOT 8192
#define LK    128      // padded LoRA K (8 shared + 64 expert + 56 zero)
#define BM    128
#define BKH   32       // K halfs per stage (64 B payload per row)
#define PADH  40       // padded row stride in halfs (80 B) -> conflict-free LDSM
#define NST   4        // pipeline stages

// ------------------------- device scratch -------------------------
__device__ __half g_xh[M_TOT * DIN];     // fp16 x
__device__ __half g_Wh[DOUT * DIN];      // fp16 base_W
__device__ __half g_Aall[LK * DIN];      // rows: 8 shared_A, 64 expert_A, 56 zero
__device__ __half g_Wlora[DOUT * LK];    // [o][j]
__device__ __half g_T[M_TOT * LK];       // scaled low-rank activations
__device__ float  g_meanpart[16 * B_ * DIN];
__device__ float  g_xmean[B_ * DIN];
__device__ float  g_colscale[B_ * LK];

// ------------------------- helpers -------------------------
__device__ __forceinline__ uint32_t s2u(const void* p) {
    uint32_t a;
    asm("{ .reg .u64 t; cvta.to.shared.u64 t, %1; cvt.u32.u64 %0, t; }"
        : "=r"(a) : "l"(p));
    return a;
}

// ------------------------- small kernels -------------------------
__global__ void prep_x(const float* __restrict__ x) {
    int bx = blockIdx.x;            // 512 blocks: b(4) * sc(16) * dc(8)
    int b  = bx >> 7;
    int sc = (bx >> 3) & 15;
    int dc = bx & 7;
    int d  = dc * 256 + threadIdx.x;
    size_t off = ((size_t)b * S_ + sc * 128) * DIN + d;
    const float* p = x + off;
    __half* q = g_xh + off;
    float s = 0.f;
    #pragma unroll 4
    for (int i = 0; i < 128; i++) {
        float v = p[(size_t)i * DIN];
        s += v;
        q[(size_t)i * DIN] = __float2half_rn(v);
    }
    g_meanpart[(sc * B_ + b) * DIN + d] = s;
}

__global__ void prep_w(const float4* __restrict__ w) {
    int i = blockIdx.x * 256 + threadIdx.x;   // 1M float4
    float4 v = w[i];
    __half2* o = (__half2*)g_Wh;
    o[i * 2]     = __floats2half2_rn(v.x, v.y);
    o[i * 2 + 1] = __floats2half2_rn(v.z, v.w);
}

__global__ void pack_kernel(const float* __restrict__ sharedA,
                            const float* __restrict__ expertA,
                            const float* __restrict__ sharedB,
                            const float* __restrict__ expertB) {
    int i = blockIdx.x * blockDim.x + threadIdx.x;
    const int NA = LK * DIN;  // 262144
    if (i < NA) {
        int j = i / DIN, k = i % DIN;
        float v = 0.f;
        if (j < 8)        v = sharedA[j * DIN + k];
        else if (j < 72)  v = expertA[(j - 8) * DIN + k];
        g_Aall[i] = __float2half_rn(v);
    } else {
        int i2 = i - NA;
        int o = i2 / LK, j = i2 % LK;
        float v = 0.f;
        if (j < 8)        v = sharedB[o * 8 + j];
        else if (j < 72) { int e = (j - 8) >> 3, r = (j - 8) & 7;
                           v = expertB[((size_t)e * DOUT + o) * 8 + r]; }
        g_Wlora[i2] = __float2half_rn(v);
    }
}

__global__ void mean_final() {
    int i = blockIdx.x * 256 + threadIdx.x;   // 0 .. B_*DIN-1
    float s = 0.f;
    #pragma unroll
    for (int p = 0; p < 16; p++) s += g_meanpart[p * (B_ * DIN) + i];
    g_xmean[i] = s * (1.0f / (float)S_);
}

__global__ void routing_kernel(const float* __restrict__ task_emb,
                               const float* __restrict__ collab_w) {
    __shared__ float slog[B_][8];
    __shared__ float srout[B_][8];
    __shared__ float scw;
    int tid = threadIdx.x, lane = tid & 31, w = tid >> 5;  // warp w -> expert w
    const float4* tev = (const float4*)(task_emb + w * DIN);
    for (int b = 0; b < B_; b++) {
        const float4* xv = (const float4*)(g_xmean + b * DIN);
        float p = 0.f;
        #pragma unroll 4
        for (int i = lane; i < DIN / 4; i += 32) {
            float4 a = xv[i], c = tev[i];
            p += a.x * c.x + a.y * c.y + a.z * c.z + a.w * c.w;
        }
        #pragma unroll
        for (int o = 16; o > 0; o >>= 1) p += __shfl_down_sync(0xffffffffu, p, o);
        if (lane == 0) slog[b][w] = p;
    }
    if (tid == 0) scw = 1.f / (1.f + expf(-collab_w[0]));
    __syncthreads();
    if (tid < B_) {
        float mx = -1e30f;
        for (int e = 0; e < 8; e++) mx = fmaxf(mx, slog[tid][e]);
        float ex[8], sm = 0.f;
        for (int e = 0; e < 8; e++) { ex[e] = expf(slog[tid][e] - mx); sm += ex[e]; }
        for (int e = 0; e < 8; e++) srout[tid][e] = ex[e] / sm;
    }
    __syncthreads();
    float cw = scw;
    for (int i = tid; i < B_ * LK; i += blockDim.x) {
        int b = i / LK, j = i % LK;
        float v = 0.f;
        if (j < 8)       v = 2.0f * cw;
        else if (j < 72) v = 2.0f * (1.f - cw) * srout[b][(j - 8) >> 3];
        g_colscale[i] = v;
    }
}

// ------------------------- fp16 mma.sync GEMM -------------------------
// C[m][n] = sum over 2 K-segments of A[m][k]*B[n][k]  (+bias) (*colscale)
// Warp grid 2x4. BN_=128 -> warp tile 64x32; BN_=256 -> warp tile 64x64.
template<int BN_, bool ADD_BIAS, bool SCALE_COLS, bool OUT_HALF>
__global__ void __launch_bounds__(256, (BN_ == 128 ? 2 : 1))
gemm_h(const __half* __restrict__ A,  int lda,
       const __half* __restrict__ Bm, int ldb,
       const __half* __restrict__ A2, int lda2,
       const __half* __restrict__ B2, int ldb2,
       int kt1, int kt2,
       void* __restrict__ Cp, int ldc,
       const float* __restrict__ bias,
       const float* __restrict__ colscale)
{
    constexpr int JT   = BN_ / 32;          // mma n8 steps per warp
    constexpr int ROWS = BM + BN_;
    constexpr int STG  = ROWS * PADH;       // halfs per stage
    constexpr int GPT  = ROWS * 4 / 256;    // 16B granules per thread per stage

    extern __shared__ __half sm[];

    const int tid  = threadIdx.x;
    const int bm   = blockIdx.y, bn = blockIdx.x;
    const int warp = tid >> 5, lane = tid & 31;
    const int wm   = warp >> 2, wn = warp & 3;
    const int KT   = kt1 + kt2;

    auto issue = [&](int kt, int slot) {
        const __half *a0, *b0; int la, lb;
        if (kt < kt1) { a0 = A;  b0 = Bm; la = lda;  lb = ldb;  }
        else          { a0 = A2; b0 = B2; la = lda2; lb = ldb2; kt -= kt1; }
        #pragma unroll
        for (int q = 0; q < GPT; q++) {
            int gid = q * 256 + tid;
            int row = gid >> 2, g = gid & 3;
            uint32_t dst = s2u(sm + slot * STG + row * PADH) + g * 16;
            const __half* src;
            if (row < BM) src = a0 + (size_t)(bm * BM + row) * la + kt * BKH + g * 8;
            else          src = b0 + (size_t)(bn * BN_ + row - BM) * lb + kt * BKH + g * 8;
            asm volatile("cp.async.cg.shared.global [%0], [%1], 16;\n"
                         :: "r"(dst), "l"(src));
        }
        asm volatile("cp.async.commit_group;\n");
    };

    float acc[4][JT][4];
    #pragma unroll
    for (int i = 0; i < 4; i++)
        #pragma unroll
        for (int j = 0; j < JT; j++)
            #pragma unroll
            for (int q = 0; q < 4; q++) acc[i][j][q] = 0.f;

    issue(0, 0); issue(1, 1); issue(2, 2);

    const int a_row  = wm * 64 + (lane & 15);                 // + i*16
    const int a_coff = (lane >> 4) << 4;                      // 0 or 16 bytes
    const int b_row0 = BM + wn * (JT * 8) + (lane & 7) + ((lane >> 4) & 1) * 8;
    const int b_coff = ((lane >> 3) & 1) << 4;

    for (int kt = 0; kt < KT; ++kt) {
        if (kt < KT - 2)       asm volatile("cp.async.wait_group 2;\n");
        else if (kt == KT - 2) asm volatile("cp.async.wait_group 1;\n");
        else                   asm volatile("cp.async.wait_group 0;\n");
        __syncthreads();
        if (kt + 3 < KT) issue(kt + 3, (kt + 3) & (NST - 1));

        int slot = kt & (NST - 1);
        uint32_t base = s2u(sm + slot * STG);

        #pragma unroll
        for (int ks = 0; ks < 2; ks++) {          // two k16 steps per BK=32
            uint32_t af[4][4], bf[JT][2];
            #pragma unroll
            for (int i = 0; i < 4; i++) {
                uint32_t addr = base + (uint32_t)(a_row + i * 16) * 80
                              + (uint32_t)(ks * 32 + a_coff);
                asm volatile(
                    "ldmatrix.sync.aligned.m8n8.x4.shared.b16 {%0,%1,%2,%3}, [%4];"
                    : "=r"(af[i][0]), "=r"(af[i][1]), "=r"(af[i][2]), "=r"(af[i][3])
                    : "r"(addr));
            }
            #pragma unroll
            for (int jn = 0; jn < JT / 2; jn++) {
                uint32_t r0, r1, r2, r3;
                uint32_t addr = base + (uint32_t)(b_row0 + jn * 16) * 80
                              + (uint32_t)(ks * 32 + b_coff);
                asm volatile(
                    "ldmatrix.sync.aligned.m8n8.x4.shared.b16 {%0,%1,%2,%3}, [%4];"
                    : "=r"(r0), "=r"(r1), "=r"(r2), "=r"(r3)
                    : "r"(addr));
                bf[jn * 2][0] = r0;     bf[jn * 2][1] = r1;
                bf[jn * 2 + 1][0] = r2; bf[jn * 2 + 1][1] = r3;
            }
            #pragma unroll
            for (int i = 0; i < 4; i++)
                #pragma unroll
                for (int j = 0; j < JT; j++) {
                    asm volatile(
                        "mma.sync.aligned.m16n8k16.row.col.f32.f16.f16.f32 "
                        "{%0,%1,%2,%3}, {%4,%5,%6,%7}, {%8,%9}, {%0,%1,%2,%3};\n"
                        : "+f"(acc[i][j][0]), "+f"(acc[i][j][1]),
                          "+f"(acc[i][j][2]), "+f"(acc[i][j][3])
                        : "r"(af[i][0]), "r"(af[i][1]), "r"(af[i][2]), "r"(af[i][3]),
                          "r"(bf[j][0]), "r"(bf[j][1]));
                }
        }
    }

    // ---- epilogue ----
    const int g = lane >> 2, tg = lane & 3;
    #pragma unroll
    for (int i = 0; i < 4; i++) {
        int m0 = bm * BM + wm * 64 + i * 16 + g;
        #pragma unroll
        for (int j = 0; j < JT; j++) {
            int n0 = bn * BN_ + wn * (JT * 8) + j * 8 + tg * 2;
            float c0 = acc[i][j][0], c1 = acc[i][j][1];
            float c2 = acc[i][j][2], c3 = acc[i][j][3];
            if (ADD_BIAS) {
                float b0v = bias[n0], b1v = bias[n0 + 1];
                c0 += b0v; c1 += b1v; c2 += b0v; c3 += b1v;
            }
            if (SCALE_COLS) {
                int bidx = m0 >> 11;   // 2048 rows per batch
                float s0 = colscale[bidx * LK + n0], s1 = colscale[bidx * LK + n0 + 1];
                c0 *= s0; c1 *= s1; c2 *= s0; c3 *= s1;
            }
            if (OUT_HALF) {
                __half2* C = (__half2*)Cp;
                C[((size_t)m0 * ldc + n0) >> 1]       = __floats2half2_rn(c0, c1);
                C[((size_t)(m0 + 8) * ldc + n0) >> 1] = __floats2half2_rn(c2, c3);
            } else {
                float* C = (float*)Cp;
                *(float2*)&C[(size_t)m0 * ldc + n0]       = make_float2(c0, c1);
                *(float2*)&C[(size_t)(m0 + 8) * ldc + n0] = make_float2(c2, c3);
            }
        }
    }
}

// ------------------------- host -------------------------
extern "C" void kernel_launch(void* const* d_in, const int* in_sizes, int n_in,
                              void* d_out, int out_size) {
    const float* x        = (const float*)d_in[0];
    const float* base_W   = (const float*)d_in[1];
    const float* base_b   = (const float*)d_in[2];
    const float* shared_A = (const float*)d_in[3];
    const float* shared_B = (const float*)d_in[4];
    const float* expert_A = (const float*)d_in[5];
    const float* expert_B = (const float*)d_in[6];
    const float* task_emb = (const float*)d_in[7];
    const float* collab_w = (const float*)d_in[8];
    float* out = (float*)d_out;
    (void)in_sizes; (void)n_in; (void)out_size;

    void *pXh, *pWh, *pAall, *pWlora, *pT, *pCS;
    cudaGetSymbolAddress(&pXh,    g_xh);
    cudaGetSymbolAddress(&pWh,    g_Wh);
    cudaGetSymbolAddress(&pAall,  g_Aall);
    cudaGetSymbolAddress(&pWlora, g_Wlora);
    cudaGetSymbolAddress(&pT,     g_T);
    cudaGetSymbolAddress(&pCS,    g_colscale);

    const int SMEM_T    = NST * (BM + 128) * PADH * 2;   //  81920
    const int SMEM_MAIN = NST * (BM + 256) * PADH * 2;   // 122880
    cudaFuncSetAttribute((const void*)gemm_h<128, false, true,  true>,
                         cudaFuncAttributeMaxDynamicSharedMemorySize, SMEM_T);
    cudaFuncSetAttribute((const void*)gemm_h<256, true,  false, false>,
                         cudaFuncAttributeMaxDynamicSharedMemorySize, SMEM_MAIN);

    prep_x<<<512, 256>>>(x);
    prep_w<<<(DOUT * DIN) / (4 * 256), 256>>>((const float4*)base_W);
    pack_kernel<<<(LK * DIN + DOUT * LK) / 256, 256>>>(shared_A, expert_A,
                                                       shared_B, expert_B);
    mean_final<<<(B_ * DIN) / 256, 256>>>();
    routing_kernel<<<1, 256>>>(task_emb, collab_w);

    // T' = colscale .* (x @ Aall^T) -> fp16 : M=8192, N=128, K=2048
    gemm_h<128, false, true, true><<<dim3(1, M_TOT / BM), 256, SMEM_T>>>(
        (const __half*)pXh, DIN, (const __half*)pAall, DIN,
        (const __half*)pXh, DIN, (const __half*)pAall, DIN,   // unused segment 2
        DIN / BKH, 0,
        pT, LK, nullptr, (const float*)pCS);

    // out = x @ W^T + b + T' @ Wlora^T : M=8192, N=2048, K=2048+128
    gemm_h<256, true, false, false><<<dim3(DOUT / 256, M_TOT / BM), 256, SMEM_MAIN>>>(
        (const __half*)pXh, DIN, (const __half*)pWh, DIN,
        (const __half*)pT,  LK,  (const __half*)pWlora, LK,
        DIN / BKH, LK / BKH,
        out, DOUT, (const float*)base_b, nullptr);
}

// round 8
// speedup vs baseline: 1.8503x; 1.8503x over previous
#include <cuda_runtime.h>
#include <cuda_fp16.h>
#include <cstdint>

#define B_    4
#define S_    2048
#define DIN   2048
#define DOUT  2048
#define M_TOT 8192
#define LK    128      // padded LoRA K (8 shared + 64 expert + 56 zero)
#define BM    128
#define BN    128
#define BKH   32       // K halfs per stage (64 B payload per row)
#define PADH  40       // padded row stride in halfs (80 B) -> conflict-free LDSM
#define NST   4        // pipeline stages
#define STAGEH ((BM + BN) * PADH)         // halfs per stage
#define SMEM_BYTES (NST * STAGEH * 2)     // 81920

// ------------------------- device scratch -------------------------
__device__ __half g_xh[M_TOT * DIN];     // fp16 x
__device__ __half g_Wh[DOUT * DIN];      // fp16 base_W
__device__ __half g_Aall[LK * DIN];      // rows: 8 shared_A, 64 expert_A, 56 zero
__device__ __half g_Wlora[DOUT * LK];    // [o][j]
__device__ __half g_T[M_TOT * LK];       // scaled low-rank activations
__device__ float  g_meanpart[16 * B_ * DIN];
__device__ float  g_xmean[B_ * DIN];
__device__ float  g_colscale[B_ * LK];

// ------------------------- helpers -------------------------
__device__ __forceinline__ uint32_t s2u(const void* p) {
    uint32_t a;
    asm("{ .reg .u64 t; cvta.to.shared.u64 t, %1; cvt.u32.u64 %0, t; }"
        : "=r"(a) : "l"(p));
    return a;
}

// ------------------------- fused prep kernel -------------------------
// blocks [0,512):     x -> fp16 + mean partials  (512*256*128 = 16.7M elems)
// blocks [512,4608):  base_W -> fp16             (4096*256 = 1M float4)
// blocks [4608,6656): pack Aall / Wlora -> fp16  (2048*256 = 512K elems)
__global__ void prep_fused(const float* __restrict__ x,
                           const float4* __restrict__ w,
                           const float* __restrict__ sharedA,
                           const float* __restrict__ expertA,
                           const float* __restrict__ sharedB,
                           const float* __restrict__ expertB) {
    int bx = blockIdx.x;
    int tid = threadIdx.x;
    if (bx < 512) {
        int b  = bx >> 7;
        int sc = (bx >> 3) & 15;
        int dc = bx & 7;
        int d  = dc * 256 + tid;
        size_t off = ((size_t)b * S_ + sc * 128) * DIN + d;
        const float* p = x + off;
        __half* q = g_xh + off;
        float s = 0.f;
        #pragma unroll 4
        for (int i = 0; i < 128; i++) {
            float v = p[(size_t)i * DIN];
            s += v;
            q[(size_t)i * DIN] = __float2half_rn(v);
        }
        g_meanpart[(sc * B_ + b) * DIN + d] = s;
    } else if (bx < 4608) {
        int i = (bx - 512) * 256 + tid;   // 0 .. 1M-1 float4 (DOUT*DIN/4)
        float4 v = w[i];
        __half2* o = (__half2*)g_Wh;
        o[i * 2]     = __floats2half2_rn(v.x, v.y);
        o[i * 2 + 1] = __floats2half2_rn(v.z, v.w);
    } else {
        int i = (bx - 4608) * 256 + tid;
        const int NA = LK * DIN;  // 262144
        if (i < NA) {
            int j = i / DIN, k = i % DIN;
            float v = 0.f;
            if (j < 8)        v = sharedA[j * DIN + k];
            else if (j < 72)  v = expertA[(j - 8) * DIN + k];
            g_Aall[i] = __float2half_rn(v);
        } else {
            int i2 = i - NA;
            int o = i2 / LK, j = i2 % LK;
            float v = 0.f;
            if (j < 8)        v = sharedB[o * 8 + j];
            else if (j < 72) { int e = (j - 8) >> 3, r = (j - 8) & 7;
                               v = expertB[((size_t)e * DOUT + o) * 8 + r]; }
            g_Wlora[i2] = __float2half_rn(v);
        }
    }
}

__global__ void mean_final() {
    int i = blockIdx.x * 256 + threadIdx.x;   // 0 .. B_*DIN-1
    float s = 0.f;
    #pragma unroll
    for (int p = 0; p < 16; p++) s += g_meanpart[p * (B_ * DIN) + i];
    g_xmean[i] = s * (1.0f / (float)S_);
}

__global__ void routing_kernel(const float* __restrict__ task_emb,
                               const float* __restrict__ collab_w) {
    __shared__ float slog[B_][8];
    __shared__ float srout[B_][8];
    __shared__ float scw;
    int tid = threadIdx.x, lane = tid & 31, w = tid >> 5;  // warp w -> expert w
    const float4* tev = (const float4*)(task_emb + w * DIN);
    for (int b = 0; b < B_; b++) {
        const float4* xv = (const float4*)(g_xmean + b * DIN);
        float p = 0.f;
        #pragma unroll 4
        for (int i = lane; i < DIN / 4; i += 32) {
            float4 a = xv[i], c = tev[i];
            p += a.x * c.x + a.y * c.y + a.z * c.z + a.w * c.w;
        }
        #pragma unroll
        for (int o = 16; o > 0; o >>= 1) p += __shfl_down_sync(0xffffffffu, p, o);
        if (lane == 0) slog[b][w] = p;
    }
    if (tid == 0) scw = 1.f / (1.f + expf(-collab_w[0]));
    __syncthreads();
    if (tid < B_) {
        float mx = -1e30f;
        for (int e = 0; e < 8; e++) mx = fmaxf(mx, slog[tid][e]);
        float ex[8], sm = 0.f;
        for (int e = 0; e < 8; e++) { ex[e] = expf(slog[tid][e] - mx); sm += ex[e]; }
        for (int e = 0; e < 8; e++) srout[tid][e] = ex[e] / sm;
    }
    __syncthreads();
    float cw = scw;
    for (int i = tid; i < B_ * LK; i += blockDim.x) {
        int b = i / LK, j = i % LK;
        float v = 0.f;
        if (j < 8)       v = 2.0f * cw;
        else if (j < 72) v = 2.0f * (1.f - cw) * srout[b][(j - 8) >> 3];
        g_colscale[i] = v;
    }
}

// ------------------------- fp16 mma.sync GEMM -------------------------
// CTA tile 128x128, 4 warps (2x2), warp tile 64x64, 2 CTAs/SM.
// C[m][n] = sum over 2 K-segments of A[m][k]*B[n][k]  (+bias) (*colscale)
template<bool ADD_BIAS, bool SCALE_COLS, bool OUT_HALF>
__global__ void __launch_bounds__(128, 2)
gemm_h(const __half* __restrict__ A,  int lda,
       const __half* __restrict__ Bm, int ldb,
       const __half* __restrict__ A2, int lda2,
       const __half* __restrict__ B2, int ldb2,
       int kt1, int kt2,
       void* __restrict__ Cp, int ldc,
       const float* __restrict__ bias,
       const float* __restrict__ colscale)
{
    constexpr int JT = 8;                   // mma n8 steps per warp (64 cols)
    extern __shared__ __half sm[];

    const int tid  = threadIdx.x;
    const int bm   = blockIdx.y, bn = blockIdx.x;
    const int warp = tid >> 5, lane = tid & 31;
    const int wm   = warp >> 1, wn = warp & 1;   // 2x2 warps, 64x64 warp tile
    const int KT   = kt1 + kt2;

    // producer: 8 x 16B cp.async per thread per stage (256 rows x 4 granules)
    auto issue = [&](int kt, int slot) {
        const __half *a0, *b0; int la, lb;
        if (kt < kt1) { a0 = A;  b0 = Bm; la = lda;  lb = ldb;  }
        else          { a0 = A2; b0 = B2; la = lda2; lb = ldb2; kt -= kt1; }
        #pragma unroll
        for (int q = 0; q < 8; q++) {
            int gid = q * 128 + tid;
            int row = gid >> 2, g = gid & 3;
            uint32_t dst = s2u(sm + slot * STAGEH + row * PADH) + g * 16;
            const __half* src;
            if (row < BM) src = a0 + (size_t)(bm * BM + row) * la + kt * BKH + g * 8;
            else          src = b0 + (size_t)(bn * BN + row - BM) * lb + kt * BKH + g * 8;
            asm volatile("cp.async.cg.shared.global [%0], [%1], 16;\n"
                         :: "r"(dst), "l"(src));
        }
        asm volatile("cp.async.commit_group;\n");
    };

    float acc[4][JT][4];
    #pragma unroll
    for (int i = 0; i < 4; i++)
        #pragma unroll
        for (int j = 0; j < JT; j++)
            #pragma unroll
            for (int q = 0; q < 4; q++) acc[i][j][q] = 0.f;

    issue(0, 0); issue(1, 1); issue(2, 2);

    const int a_row  = wm * 64 + (lane & 15);                 // + i*16
    const int a_coff = (lane >> 4) << 4;                      // 0 or 16 bytes
    const int b_row0 = BM + wn * 64 + (lane & 7) + ((lane >> 4) & 1) * 8;
    const int b_coff = ((lane >> 3) & 1) << 4;

    for (int kt = 0; kt < KT; ++kt) {
        if (kt < KT - 2)       asm volatile("cp.async.wait_group 2;\n");
        else if (kt == KT - 2) asm volatile("cp.async.wait_group 1;\n");
        else                   asm volatile("cp.async.wait_group 0;\n");
        __syncthreads();
        if (kt + 3 < KT) issue(kt + 3, (kt + 3) & (NST - 1));

        int slot = kt & (NST - 1);
        uint32_t base = s2u(sm + slot * STAGEH);

        #pragma unroll
        for (int ks = 0; ks < 2; ks++) {          // two k16 steps per BK=32
            uint32_t af[4][4], bf[JT][2];
            #pragma unroll
            for (int i = 0; i < 4; i++) {
                uint32_t addr = base + (uint32_t)(a_row + i * 16) * 80
                              + (uint32_t)(ks * 32 + a_coff);
                asm volatile(
                    "ldmatrix.sync.aligned.m8n8.x4.shared.b16 {%0,%1,%2,%3}, [%4];"
                    : "=r"(af[i][0]), "=r"(af[i][1]), "=r"(af[i][2]), "=r"(af[i][3])
                    : "r"(addr));
            }
            #pragma unroll
            for (int jn = 0; jn < JT / 2; jn++) {
                uint32_t r0, r1, r2, r3;
                uint32_t addr = base + (uint32_t)(b_row0 + jn * 16) * 80
                              + (uint32_t)(ks * 32 + b_coff);
                asm volatile(
                    "ldmatrix.sync.aligned.m8n8.x4.shared.b16 {%0,%1,%2,%3}, [%4];"
                    : "=r"(r0), "=r"(r1), "=r"(r2), "=r"(r3)
                    : "r"(addr));
                bf[jn * 2][0] = r0;     bf[jn * 2][1] = r1;
                bf[jn * 2 + 1][0] = r2; bf[jn * 2 + 1][1] = r3;
            }
            #pragma unroll
            for (int i = 0; i < 4; i++)
                #pragma unroll
                for (int j = 0; j < JT; j++) {
                    asm volatile(
                        "mma.sync.aligned.m16n8k16.row.col.f32.f16.f16.f32 "
                        "{%0,%1,%2,%3}, {%4,%5,%6,%7}, {%8,%9}, {%0,%1,%2,%3};\n"
                        : "+f"(acc[i][j][0]), "+f"(acc[i][j][1]),
                          "+f"(acc[i][j][2]), "+f"(acc[i][j][3])
                        : "r"(af[i][0]), "r"(af[i][1]), "r"(af[i][2]), "r"(af[i][3]),
                          "r"(bf[j][0]), "r"(bf[j][1]));
                }
        }
    }

    // ---- epilogue ----
    const int g = lane >> 2, tg = lane & 3;
    #pragma unroll
    for (int i = 0; i < 4; i++) {
        int m0 = bm * BM + wm * 64 + i * 16 + g;
        #pragma unroll
        for (int j = 0; j < JT; j++) {
            int n0 = bn * BN + wn * 64 + j * 8 + tg * 2;
            float c0 = acc[i][j][0], c1 = acc[i][j][1];
            float c2 = acc[i][j][2], c3 = acc[i][j][3];
            if (ADD_BIAS) {
                float b0v = bias[n0], b1v = bias[n0 + 1];
                c0 += b0v; c1 += b1v; c2 += b0v; c3 += b1v;
            }
            if (SCALE_COLS) {
                int bidx = m0 >> 11;   // 2048 rows per batch
                float s0 = colscale[bidx * LK + n0], s1 = colscale[bidx * LK + n0 + 1];
                c0 *= s0; c1 *= s1; c2 *= s0; c3 *= s1;
            }
            if (OUT_HALF) {
                __half2* C = (__half2*)Cp;
                C[((size_t)m0 * ldc + n0) >> 1]       = __floats2half2_rn(c0, c1);
                C[((size_t)(m0 + 8) * ldc + n0) >> 1] = __floats2half2_rn(c2, c3);
            } else {
                float* C = (float*)Cp;
                *(float2*)&C[(size_t)m0 * ldc + n0]       = make_float2(c0, c1);
                *(float2*)&C[(size_t)(m0 + 8) * ldc + n0] = make_float2(c2, c3);
            }
        }
    }
}

// ------------------------- host -------------------------
extern "C" void kernel_launch(void* const* d_in, const int* in_sizes, int n_in,
                              void* d_out, int out_size) {
    const float* x        = (const float*)d_in[0];
    const float* base_W   = (const float*)d_in[1];
    const float* base_b   = (const float*)d_in[2];
    const float* shared_A = (const float*)d_in[3];
    const float* shared_B = (const float*)d_in[4];
    const float* expert_A = (const float*)d_in[5];
    const float* expert_B = (const float*)d_in[6];
    const float* task_emb = (const float*)d_in[7];
    const float* collab_w = (const float*)d_in[8];
    float* out = (float*)d_out;
    (void)in_sizes; (void)n_in; (void)out_size;

    void *pXh, *pWh, *pAall, *pWlora, *pT, *pCS;
    cudaGetSymbolAddress(&pXh,    g_xh);
    cudaGetSymbolAddress(&pWh,    g_Wh);
    cudaGetSymbolAddress(&pAall,  g_Aall);
    cudaGetSymbolAddress(&pWlora, g_Wlora);
    cudaGetSymbolAddress(&pT,     g_T);
    cudaGetSymbolAddress(&pCS,    g_colscale);

    cudaFuncSetAttribute((const void*)gemm_h<false, true,  true>,
                         cudaFuncAttributeMaxDynamicSharedMemorySize, SMEM_BYTES);
    cudaFuncSetAttribute((const void*)gemm_h<true,  false, false>,
                         cudaFuncAttributeMaxDynamicSharedMemorySize, SMEM_BYTES);

    prep_fused<<<6656, 256>>>(x, (const float4*)base_W, shared_A, expert_A,
                              shared_B, expert_B);
    mean_final<<<(B_ * DIN) / 256, 256>>>();
    routing_kernel<<<1, 256>>>(task_emb, collab_w);

    // T' = colscale .* (x @ Aall^T) -> fp16 : M=8192, N=128, K=2048
    gemm_h<false, true, true><<<dim3(1, M_TOT / BM), 128, SMEM_BYTES>>>(
        (const __half*)pXh, DIN, (const __half*)pAall, DIN,
        (const __half*)pXh, DIN, (const __half*)pAall, DIN,   // unused segment 2
        DIN / BKH, 0,
        pT, LK, nullptr, (const float*)pCS);

    // out = x @ W^T + b + T' @ Wlora^T : M=8192, N=2048, K=2048+128
    gemm_h<true, false, false><<<dim3(DOUT / BN, M_TOT / BM), 128, SMEM_BYTES>>>(
        (const __half*)pXh, DIN, (const __half*)pWh, DIN,
        (const __half*)pT,  LK,  (const __half*)pWlora, LK,
        DIN / BKH, LK / BKH,
        out, DOUT, (const float*)base_b, nullptr);
}

// round 9
// speedup vs baseline: 2.0170x; 1.0901x over previous
#include <cuda_runtime.h>
#include <cuda_fp16.h>
#include <cstdint>

#define B_    4
#define S_    2048
#define DIN   2048
#define DOUT  2048
#define M_TOT 8192
#define LK    128      // padded LoRA K (8 shared + 64 expert + 56 zero)
#define BM    128
#define BN    128
#define BKH   32       // K halfs per stage (64 B payload per row)
#define PADH  40       // padded row stride in halfs (80 B) -> conflict-free LDSM
#define NST   5        // pipeline stages
#define STAGEH ((BM + BN) * PADH)         // halfs per stage
#define SMEM_BYTES (NST * STAGEH * 2)     // 102400
#define KSPLIT 4

// ------------------------- device scratch -------------------------
__device__ __half g_xh[M_TOT * DIN];     // fp16 x
__device__ __half g_Wh[DOUT * DIN];      // fp16 base_W
__device__ __half g_Aall[LK * DIN];      // rows: 8 shared_A, 64 expert_A, 56 zero
__device__ __half g_Wlora[DOUT * LK];    // [o][j]
__device__ __half g_T[M_TOT * LK];       // scaled low-rank activations
__device__ float  g_Tpart[KSPLIT * M_TOT * LK];  // split-K partials (16 MB)
__device__ float  g_meanpart[16 * B_ * DIN];
__device__ float  g_xmean[B_ * DIN];
__device__ float  g_colscale[B_ * LK];

// ------------------------- helpers -------------------------
__device__ __forceinline__ uint32_t s2u(const void* p) {
    uint32_t a;
    asm("{ .reg .u64 t; cvta.to.shared.u64 t, %1; cvt.u32.u64 %0, t; }"
        : "=r"(a) : "l"(p));
    return a;
}

// ------------------------- fused prep kernel -------------------------
// blocks [0,512):     x -> fp16 + mean partials
// blocks [512,4608):  base_W -> fp16             (4096*256 = 1M float4)
// blocks [4608,6656): pack Aall / Wlora -> fp16
__global__ void prep_fused(const float* __restrict__ x,
                           const float4* __restrict__ w,
                           const float* __restrict__ sharedA,
                           const float* __restrict__ expertA,
                           const float* __restrict__ sharedB,
                           const float* __restrict__ expertB) {
    int bx = blockIdx.x;
    int tid = threadIdx.x;
    if (bx < 512) {
        int b  = bx >> 7;
        int sc = (bx >> 3) & 15;
        int dc = bx & 7;
        int d  = dc * 256 + tid;
        size_t off = ((size_t)b * S_ + sc * 128) * DIN + d;
        const float* p = x + off;
        __half* q = g_xh + off;
        float s = 0.f;
        #pragma unroll 4
        for (int i = 0; i < 128; i++) {
            float v = p[(size_t)i * DIN];
            s += v;
            q[(size_t)i * DIN] = __float2half_rn(v);
        }
        g_meanpart[(sc * B_ + b) * DIN + d] = s;
    } else if (bx < 4608) {
        int i = (bx - 512) * 256 + tid;   // 0 .. 1M-1 float4 (DOUT*DIN/4)
        float4 v = w[i];
        __half2* o = (__half2*)g_Wh;
        o[i * 2]     = __floats2half2_rn(v.x, v.y);
        o[i * 2 + 1] = __floats2half2_rn(v.z, v.w);
    } else {
        int i = (bx - 4608) * 256 + tid;
        const int NA = LK * DIN;  // 262144
        if (i < NA) {
            int j = i / DIN, k = i % DIN;
            float v = 0.f;
            if (j < 8)        v = sharedA[j * DIN + k];
            else if (j < 72)  v = expertA[(j - 8) * DIN + k];
            g_Aall[i] = __float2half_rn(v);
        } else {
            int i2 = i - NA;
            int o = i2 / LK, j = i2 % LK;
            float v = 0.f;
            if (j < 8)        v = sharedB[o * 8 + j];
            else if (j < 72) { int e = (j - 8) >> 3, r = (j - 8) & 7;
                               v = expertB[((size_t)e * DOUT + o) * 8 + r]; }
            g_Wlora[i2] = __float2half_rn(v);
        }
    }
}

__global__ void mean_final() {
    int i = blockIdx.x * 256 + threadIdx.x;   // 0 .. B_*DIN-1
    float s = 0.f;
    #pragma unroll
    for (int p = 0; p < 16; p++) s += g_meanpart[p * (B_ * DIN) + i];
    g_xmean[i] = s * (1.0f / (float)S_);
}

__global__ void routing_kernel(const float* __restrict__ task_emb,
                               const float* __restrict__ collab_w) {
    __shared__ float slog[B_][8];
    __shared__ float srout[B_][8];
    __shared__ float scw;
    int tid = threadIdx.x, lane = tid & 31, w = tid >> 5;  // warp w -> expert w
    const float4* tev = (const float4*)(task_emb + w * DIN);
    for (int b = 0; b < B_; b++) {
        const float4* xv = (const float4*)(g_xmean + b * DIN);
        float p = 0.f;
        #pragma unroll 4
        for (int i = lane; i < DIN / 4; i += 32) {
            float4 a = xv[i], c = tev[i];
            p += a.x * c.x + a.y * c.y + a.z * c.z + a.w * c.w;
        }
        #pragma unroll
        for (int o = 16; o > 0; o >>= 1) p += __shfl_down_sync(0xffffffffu, p, o);
        if (lane == 0) slog[b][w] = p;
    }
    if (tid == 0) scw = 1.f / (1.f + expf(-collab_w[0]));
    __syncthreads();
    if (tid < B_) {
        float mx = -1e30f;
        for (int e = 0; e < 8; e++) mx = fmaxf(mx, slog[tid][e]);
        float ex[8], sm = 0.f;
        for (int e = 0; e < 8; e++) { ex[e] = expf(slog[tid][e] - mx); sm += ex[e]; }
        for (int e = 0; e < 8; e++) srout[tid][e] = ex[e] / sm;
    }
    __syncthreads();
    float cw = scw;
    for (int i = tid; i < B_ * LK; i += blockDim.x) {
        int b = i / LK, j = i % LK;
        float v = 0.f;
        if (j < 8)       v = 2.0f * cw;
        else if (j < 72) v = 2.0f * (1.f - cw) * srout[b][(j - 8) >> 3];
        g_colscale[i] = v;
    }
}

// reduce split-K partials, apply colscale, convert to fp16
__global__ void t_reduce() {
    int i = blockIdx.x * 256 + threadIdx.x;   // 0 .. M_TOT*LK-1
    const int NP = M_TOT * LK;
    float s = g_Tpart[i] + g_Tpart[i + NP] + g_Tpart[i + 2 * NP] + g_Tpart[i + 3 * NP];
    int m = i >> 7, j = i & (LK - 1);
    int b = m >> 11;
    g_T[i] = __float2half_rn(s * g_colscale[b * LK + j]);
}

// ------------------------- fp16 mma.sync GEMM -------------------------
// CTA tile 128x128, 4 warps (2x2), warp tile 64x64, 2 CTAs/SM.
// SPLITK: blockIdx.z selects a K-chunk of kt1 tiles; writes fp32 partial.
template<bool ADD_BIAS, bool SCALE_COLS, bool OUT_HALF, bool SPLITK>
__global__ void __launch_bounds__(128, 2)
gemm_h(const __half* __restrict__ A,  int lda,
       const __half* __restrict__ Bm, int ldb,
       const __half* __restrict__ A2, int lda2,
       const __half* __restrict__ B2, int ldb2,
       int kt1, int kt2,
       void* __restrict__ Cp, int ldc,
       const float* __restrict__ bias,
       const float* __restrict__ colscale)
{
    constexpr int JT = 8;                   // mma n8 steps per warp (64 cols)
    extern __shared__ __half sm[];

    const int tid  = threadIdx.x;
    const int bm   = blockIdx.y, bn = blockIdx.x;
    const int warp = tid >> 5, lane = tid & 31;
    const int wm   = warp >> 1, wn = warp & 1;   // 2x2 warps, 64x64 warp tile
    const int KT   = kt1 + kt2;

    if (SPLITK) {
        size_t koff = (size_t)blockIdx.z * kt1 * BKH;
        A  += koff;  Bm += koff;
        Cp = (void*)((float*)Cp + (size_t)blockIdx.z * M_TOT * (size_t)ldc);
    }

    // producer: 8 x 16B cp.async per thread per stage (256 rows x 4 granules)
    auto issue = [&](int kt, int slot) {
        const __half *a0, *b0; int la, lb;
        if (kt < kt1) { a0 = A;  b0 = Bm; la = lda;  lb = ldb;  }
        else          { a0 = A2; b0 = B2; la = lda2; lb = ldb2; kt -= kt1; }
        #pragma unroll
        for (int q = 0; q < 8; q++) {
            int gid = q * 128 + tid;
            int row = gid >> 2, g = gid & 3;
            uint32_t dst = s2u(sm + slot * STAGEH + row * PADH) + g * 16;
            const __half* src;
            if (row < BM) src = a0 + (size_t)(bm * BM + row) * la + kt * BKH + g * 8;
            else          src = b0 + (size_t)(bn * BN + row - BM) * lb + kt * BKH + g * 8;
            asm volatile("cp.async.cg.shared.global [%0], [%1], 16;\n"
                         :: "r"(dst), "l"(src));
        }
        asm volatile("cp.async.commit_group;\n");
    };

    float acc[4][JT][4];
    #pragma unroll
    for (int i = 0; i < 4; i++)
        #pragma unroll
        for (int j = 0; j < JT; j++)
            #pragma unroll
            for (int q = 0; q < 4; q++) acc[i][j][q] = 0.f;

    issue(0, 0); issue(1, 1); issue(2, 2); issue(3, 3);

    const int a_row  = wm * 64 + (lane & 15);                 // + i*16
    const int a_coff = (lane >> 4) << 4;                      // 0 or 16 bytes
    const int b_row0 = BM + wn * 64 + (lane & 7) + ((lane >> 4) & 1) * 8;
    const int b_coff = ((lane >> 3) & 1) << 4;

    for (int kt = 0; kt < KT; ++kt) {
        int rem = KT - kt - 1;                 // stages still to be consumed after this
        if (rem >= 3)      asm volatile("cp.async.wait_group 3;\n");
        else if (rem == 2) asm volatile("cp.async.wait_group 2;\n");
        else if (rem == 1) asm volatile("cp.async.wait_group 1;\n");
        else               asm volatile("cp.async.wait_group 0;\n");
        __syncthreads();
        if (kt + 4 < KT) issue(kt + 4, (kt + 4) % NST);

        int slot = kt % NST;
        uint32_t base = s2u(sm + slot * STAGEH);

        #pragma unroll
        for (int ks = 0; ks < 2; ks++) {          // two k16 steps per BK=32
            uint32_t af[4][4], bf[JT][2];
            #pragma unroll
            for (int i = 0; i < 4; i++) {
                uint32_t addr = base + (uint32_t)(a_row + i * 16) * 80
                              + (uint32_t)(ks * 32 + a_coff);
                asm volatile(
                    "ldmatrix.sync.aligned.m8n8.x4.shared.b16 {%0,%1,%2,%3}, [%4];"
                    : "=r"(af[i][0]), "=r"(af[i][1]), "=r"(af[i][2]), "=r"(af[i][3])
                    : "r"(addr));
            }
            #pragma unroll
            for (int jn = 0; jn < JT / 2; jn++) {
                uint32_t r0, r1, r2, r3;
                uint32_t addr = base + (uint32_t)(b_row0 + jn * 16) * 80
                              + (uint32_t)(ks * 32 + b_coff);
                asm volatile(
                    "ldmatrix.sync.aligned.m8n8.x4.shared.b16 {%0,%1,%2,%3}, [%4];"
                    : "=r"(r0), "=r"(r1), "=r"(r2), "=r"(r3)
                    : "r"(addr));
                bf[jn * 2][0] = r0;     bf[jn * 2][1] = r1;
                bf[jn * 2 + 1][0] = r2; bf[jn * 2 + 1][1] = r3;
            }
            #pragma unroll
            for (int i = 0; i < 4; i++)
                #pragma unroll
                for (int j = 0; j < JT; j++) {
                    asm volatile(
                        "mma.sync.aligned.m16n8k16.row.col.f32.f16.f16.f32 "
                        "{%0,%1,%2,%3}, {%4,%5,%6,%7}, {%8,%9}, {%0,%1,%2,%3};\n"
                        : "+f"(acc[i][j][0]), "+f"(acc[i][j][1]),
                          "+f"(acc[i][j][2]), "+f"(acc[i][j][3])
                        : "r"(af[i][0]), "r"(af[i][1]), "r"(af[i][2]), "r"(af[i][3]),
                          "r"(bf[j][0]), "r"(bf[j][1]));
                }
        }
    }

    // ---- epilogue ----
    const int g = lane >> 2, tg = lane & 3;
    #pragma unroll
    for (int i = 0; i < 4; i++) {
        int m0 = bm * BM + wm * 64 + i * 16 + g;
        #pragma unroll
        for (int j = 0; j < JT; j++) {
            int n0 = bn * BN + wn * 64 + j * 8 + tg * 2;
            float c0 = acc[i][j][0], c1 = acc[i][j][1];
            float c2 = acc[i][j][2], c3 = acc[i][j][3];
            if (ADD_BIAS) {
                float b0v = bias[n0], b1v = bias[n0 + 1];
                c0 += b0v; c1 += b1v; c2 += b0v; c3 += b1v;
            }
            if (SCALE_COLS) {
                int bidx = m0 >> 11;   // 2048 rows per batch
                float s0 = colscale[bidx * LK + n0], s1 = colscale[bidx * LK + n0 + 1];
                c0 *= s0; c1 *= s1; c2 *= s0; c3 *= s1;
            }
            if (OUT_HALF) {
                __half2* C = (__half2*)Cp;
                C[((size_t)m0 * ldc + n0) >> 1]       = __floats2half2_rn(c0, c1);
                C[((size_t)(m0 + 8) * ldc + n0) >> 1] = __floats2half2_rn(c2, c3);
            } else {
                float* C = (float*)Cp;
                *(float2*)&C[(size_t)m0 * ldc + n0]       = make_float2(c0, c1);
                *(float2*)&C[(size_t)(m0 + 8) * ldc + n0] = make_float2(c2, c3);
            }
        }
    }
}

// ------------------------- host -------------------------
extern "C" void kernel_launch(void* const* d_in, const int* in_sizes, int n_in,
                              void* d_out, int out_size) {
    const float* x        = (const float*)d_in[0];
    const float* base_W   = (const float*)d_in[1];
    const float* base_b   = (const float*)d_in[2];
    const float* shared_A = (const float*)d_in[3];
    const float* shared_B = (const float*)d_in[4];
    const float* expert_A = (const float*)d_in[5];
    const float* expert_B = (const float*)d_in[6];
    const float* task_emb = (const float*)d_in[7];
    const float* collab_w = (const float*)d_in[8];
    float* out = (float*)d_out;
    (void)in_sizes; (void)n_in; (void)out_size;

    void *pXh, *pWh, *pAall, *pWlora, *pT, *pTp;
    cudaGetSymbolAddress(&pXh,    g_xh);
    cudaGetSymbolAddress(&pWh,    g_Wh);
    cudaGetSymbolAddress(&pAall,  g_Aall);
    cudaGetSymbolAddress(&pWlora, g_Wlora);
    cudaGetSymbolAddress(&pT,     g_T);
    cudaGetSymbolAddress(&pTp,    g_Tpart);

    cudaFuncSetAttribute((const void*)gemm_h<false, false, false, true>,
                         cudaFuncAttributeMaxDynamicSharedMemorySize, SMEM_BYTES);
    cudaFuncSetAttribute((const void*)gemm_h<true,  false, false, false>,
                         cudaFuncAttributeMaxDynamicSharedMemorySize, SMEM_BYTES);

    prep_fused<<<6656, 256>>>(x, (const float4*)base_W, shared_A, expert_A,
                              shared_B, expert_B);
    mean_final<<<(B_ * DIN) / 256, 256>>>();
    routing_kernel<<<1, 256>>>(task_emb, collab_w);

    // T partials: x @ Aall^T split-K x4 : M=8192, N=128, K=512 per split
    gemm_h<false, false, false, true>
        <<<dim3(1, M_TOT / BM, KSPLIT), 128, SMEM_BYTES>>>(
        (const __half*)pXh, DIN, (const __half*)pAall, DIN,
        (const __half*)pXh, DIN, (const __half*)pAall, DIN,   // unused segment 2
        (DIN / BKH) / KSPLIT, 0,
        pTp, LK, nullptr, nullptr);

    // reduce + colscale + fp16 convert
    t_reduce<<<(M_TOT * LK) / 256, 256>>>();

    // out = x @ W^T + b + T' @ Wlora^T : M=8192, N=2048, K=2048+128
    gemm_h<true, false, false, false>
        <<<dim3(DOUT / BN, M_TOT / BM), 128, SMEM_BYTES>>>(
        (const __half*)pXh, DIN, (const __half*)pWh, DIN,
        (const __half*)pT,  LK,  (const __half*)pWlora, LK,
        DIN / BKH, LK / BKH,
        out, DOUT, (const float*)base_b, nullptr);
}